// round 4
// baseline (speedup 1.0000x reference)
#include <cuda_runtime.h>
#include <math.h>

#define NCTA 128
#define NTH  256
#define Bsz  256
#define Tlen 1024
#define Hdim 256
#define K2n  128   // Hdim / 2 unit-pairs

// Persistent state, exchanged through L2 (double-buffered by step parity).
// Layout: [pair k2][batch b] packed float2 {h[2*k2][b], h[2*k2+1][b]} as u64.
__device__ unsigned long long g_h0p[2][K2n * Bsz];
__device__ unsigned long long g_h1p[2][K2n * Bsz];
__device__ unsigned g_count = 0;   // grid barrier arrival counter (monotonic per launch)
__device__ unsigned g_done  = 0;   // end-of-kernel reset rendezvous

union F2U { float2 f; unsigned long long u; };

__device__ __forceinline__ unsigned long long pack2(float a, float b) {
    F2U v; v.f.x = a; v.f.y = b; return v.u;
}
__device__ __forceinline__ float2 unpack2(unsigned long long u) {
    F2U v; v.u = u; return v.f;
}
// Blackwell packed fp32x2 FMA: 2 exact fp32 MACs per instruction.
__device__ __forceinline__ unsigned long long ffma2(unsigned long long a,
                                                    unsigned long long b,
                                                    unsigned long long c) {
    unsigned long long d;
    asm("fma.rn.f32x2 %0, %1, %2, %3;" : "=l"(d) : "l"(a), "l"(b), "l"(c));
    return d;
}
__device__ __forceinline__ float redsum(unsigned long long a) {
    float2 v = unpack2(a); return v.x + v.y;
}
__device__ __forceinline__ float sigf(float x) {
    return __fdividef(1.0f, 1.0f + __expf(-x));
}
__device__ __forceinline__ float tanhf_(float x) {
    // tanh(x) = 2*sigmoid(2x) - 1 ; saturates correctly at +-1 for large |x|
    return fmaf(2.0f, sigf(2.0f * x), -1.0f);
}

// Grid-wide barrier over NCTA co-resident CTAs (grid <= #SMs, 1 CTA/SM).
__device__ __forceinline__ void grid_bar(unsigned target) {
    __syncthreads();
    if (threadIdx.x == 0) {
        __threadfence();              // publish this CTA's global stores
        atomicAdd(&g_count, 1u);
        unsigned v;
        do {
            asm volatile("ld.acquire.gpu.u32 %0, [%1];" : "=r"(v) : "l"(&g_count));
        } while (v < target);
    }
    __syncthreads();
}

__global__ void __launch_bounds__(NTH, 1)
lstm_fused(const float* __restrict__ x,
           const float* __restrict__ Wih0, const float* __restrict__ Whh0,
           const float* __restrict__ bih0, const float* __restrict__ bhh0,
           const float* __restrict__ Wih1, const float* __restrict__ Whh1,
           const float* __restrict__ bih1, const float* __restrict__ bhh1,
           const float* __restrict__ Wlin, const float* __restrict__ blin,
           float* __restrict__ out)
{
    // Per-CTA weight slabs, pair-packed for f32x2:
    // sW[k2*4+q] : .x = {W[q*H+u0][2k2], W[q*H+u0][2k2+1]}
    //              .y = same for unit u0+1
    __shared__ ulonglong2 sW0 [K2n * 4];   // W_hh0 rows of owned units (8 KB)
    __shared__ ulonglong2 sW1i[K2n * 4];   // W_ih1
    __shared__ ulonglong2 sW1h[K2n * 4];   // W_hh1
    __shared__ float sWlin[Hdim];
    __shared__ float sRed[8];

    const int tid = threadIdx.x;           // tid == batch index b
    const int cta = blockIdx.x;
    const int u0  = 2 * cta;               // owned unit pair (both layers)

    // ---- one-time staging ----
    for (int e = tid; e < K2n * 4; e += NTH) {
        int k2 = e >> 2, q = e & 3;
        int base = (q * Hdim + u0) * Hdim + 2 * k2;
        sW0[e]  = make_ulonglong2(pack2(Whh0[base],        Whh0[base + 1]),
                                  pack2(Whh0[base + Hdim], Whh0[base + Hdim + 1]));
        sW1i[e] = make_ulonglong2(pack2(Wih1[base],        Wih1[base + 1]),
                                  pack2(Wih1[base + Hdim], Wih1[base + Hdim + 1]));
        sW1h[e] = make_ulonglong2(pack2(Whh1[base],        Whh1[base + 1]),
                                  pack2(Whh1[base + Hdim], Whh1[base + Hdim + 1]));
    }
    sWlin[tid] = Wlin[tid];

    float wx[4][2], bs0[4][2], bs1[4][2];
    #pragma unroll
    for (int q = 0; q < 4; ++q)
        #pragma unroll
        for (int j = 0; j < 2; ++j) {
            int g = q * Hdim + u0 + j;
            wx[q][j]  = Wih0[g];               // input dim == 1
            bs0[q][j] = bih0[g] + bhh0[g];
            bs1[q][j] = bih1[g] + bhh1[g];
        }
    const float bl = blin[0];

    // zero initial h state (parity-0 buffers); c state lives in registers
    g_h0p[0][cta * Bsz + tid] = 0ull;
    g_h1p[0][cta * Bsz + tid] = 0ull;
    float c0r[2] = {0.f, 0.f}, c1r[2] = {0.f, 0.f};

    unsigned nbar = 1;
    grid_bar(nbar * NCTA); nbar++;         // init barrier

    for (int t = 0; t < Tlen; ++t) {
        const int pr = t & 1, nx = pr ^ 1;

        // ================= layer 0: gates = x*Wih0 + h0_prev @ Whh0^T =================
        unsigned long long acc[4][2];
        #pragma unroll
        for (int q = 0; q < 4; ++q) { acc[q][0] = 0ull; acc[q][1] = 0ull; }

        const unsigned long long* __restrict__ hp = g_h0p[pr];
        #pragma unroll 8
        for (int k2 = 0; k2 < K2n; ++k2) {
            unsigned long long h2 = __ldcg(hp + k2 * Bsz + tid);   // coalesced, L2-coherent
            #pragma unroll
            for (int q = 0; q < 4; ++q) {
                ulonglong2 w = sW0[k2 * 4 + q];                    // broadcast LDS.128
                acc[q][0] = ffma2(h2, w.x, acc[q][0]);
                acc[q][1] = ffma2(h2, w.y, acc[q][1]);
            }
        }
        float xv = __ldg(x + tid * Tlen + t);
        float h0w[2];
        #pragma unroll
        for (int j = 0; j < 2; ++j) {
            float gi = redsum(acc[0][j]) + fmaf(wx[0][j], xv, bs0[0][j]);
            float gf = redsum(acc[1][j]) + fmaf(wx[1][j], xv, bs0[1][j]);
            float gg = redsum(acc[2][j]) + fmaf(wx[2][j], xv, bs0[2][j]);
            float go = redsum(acc[3][j]) + fmaf(wx[3][j], xv, bs0[3][j]);
            float cn = sigf(gf) * c0r[j] + sigf(gi) * tanhf_(gg);
            c0r[j] = cn;
            h0w[j] = sigf(go) * tanhf_(cn);
        }
        g_h0p[nx][cta * Bsz + tid] = pack2(h0w[0], h0w[1]);

        grid_bar(nbar * NCTA); nbar++;     // all h0_new published

        // ============ layer 1: gates = h0_new @ Wih1^T + h1_prev @ Whh1^T ============
        unsigned long long acc2[4][2];
        #pragma unroll
        for (int q = 0; q < 4; ++q) { acc2[q][0] = 0ull; acc2[q][1] = 0ull; }

        const unsigned long long* __restrict__ ha = g_h0p[nx];
        const unsigned long long* __restrict__ hb = g_h1p[pr];
        #pragma unroll 4
        for (int k2 = 0; k2 < K2n; ++k2) {
            unsigned long long va = __ldcg(ha + k2 * Bsz + tid);
            unsigned long long vb = __ldcg(hb + k2 * Bsz + tid);
            #pragma unroll
            for (int q = 0; q < 4; ++q) {
                ulonglong2 wi = sW1i[k2 * 4 + q];
                ulonglong2 wh = sW1h[k2 * 4 + q];
                acc2[q][0] = ffma2(va, wi.x, acc2[q][0]);
                acc2[q][1] = ffma2(va, wi.y, acc2[q][1]);
                acc2[q][0] = ffma2(vb, wh.x, acc2[q][0]);
                acc2[q][1] = ffma2(vb, wh.y, acc2[q][1]);
            }
        }
        float h1w[2];
        #pragma unroll
        for (int j = 0; j < 2; ++j) {
            float gi = redsum(acc2[0][j]) + bs1[0][j];
            float gf = redsum(acc2[1][j]) + bs1[1][j];
            float gg = redsum(acc2[2][j]) + bs1[2][j];
            float go = redsum(acc2[3][j]) + bs1[3][j];
            float cn = sigf(gf) * c1r[j] + sigf(gi) * tanhf_(gg);
            c1r[j] = cn;
            h1w[j] = sigf(go) * tanhf_(cn);
        }
        g_h1p[nx][cta * Bsz + tid] = pack2(h1w[0], h1w[1]);

        grid_bar(nbar * NCTA); nbar++;     // all h1_new published

        // ================= output: out[bb, t] = h1[t, bb, :] . Wlin + blin ============
        {
            const unsigned long long* __restrict__ hc = g_h1p[nx];
            int half = tid >> 7;           // threads 0-127 -> batch u0, 128-255 -> u0+1
            int kk   = tid & 127;
            int bb   = u0 + half;
            float2 hv = unpack2(__ldcg(hc + kk * Bsz + bb));
            float part = hv.x * sWlin[2 * kk] + hv.y * sWlin[2 * kk + 1];
            #pragma unroll
            for (int off = 16; off > 0; off >>= 1)
                part += __shfl_down_sync(0xffffffffu, part, off);
            if ((tid & 31) == 0) sRed[tid >> 5] = part;
            __syncthreads();
            if (tid == 0)
                out[(u0 + 0) * Tlen + t] = sRed[0] + sRed[1] + sRed[2] + sRed[3] + bl;
            if (tid == 128)
                out[(u0 + 1) * Tlen + t] = sRed[4] + sRed[5] + sRed[6] + sRed[7] + bl;
            __syncthreads();               // protect sRed reuse next step
        }
    }

    // Reset barrier counters for the next launch (last CTA to finish does it;
    // at that point every other CTA has completed its final poll).
    __syncthreads();
    if (tid == 0) {
        __threadfence();
        unsigned old = atomicAdd(&g_done, 1u);
        if (old == NCTA - 1) {
            atomicExch(&g_count, 0u);
            atomicExch(&g_done, 0u);
        }
    }
}

extern "C" void kernel_launch(void* const* d_in, const int* in_sizes, int n_in,
                              void* d_out, int out_size) {
    (void)in_sizes; (void)n_in; (void)out_size;
    // metadata order: x, W_ih0, W_hh0, b_ih0, b_hh0, W_ih1, W_hh1, b_ih1, b_hh1,
    //                 W_lin, b_lin, future(=0, ignored)
    lstm_fused<<<NCTA, NTH>>>(
        (const float*)d_in[0],
        (const float*)d_in[1], (const float*)d_in[2],
        (const float*)d_in[3], (const float*)d_in[4],
        (const float*)d_in[5], (const float*)d_in[6],
        (const float*)d_in[7], (const float*)d_in[8],
        (const float*)d_in[9], (const float*)d_in[10],
        (float*)d_out);
}

// round 5
// speedup vs baseline: 1.3588x; 1.3588x over previous
#include <cuda_runtime.h>
#include <math.h>

#define NCTA 128
#define NTH  512
#define Bsz  256
#define Tlen 1024
#define Hdim 256
#define K2n  128   // Hdim/2 unit-pairs (k dimension in f32x2 lanes)
#define K2PT 32    // K2n / 4 k-split groups

// Persistent state, exchanged through L2 (double-buffered by step parity).
// Layout: [pair k2][batch b] packed float2 {h[2k2][b], h[2k2+1][b]} as u64.
__device__ unsigned long long g_h0p[2][K2n * Bsz];
__device__ unsigned long long g_h1p[2][K2n * Bsz];
__device__ float g_xT[Tlen * Bsz];   // x transposed: [t][b]
__device__ unsigned g_count = 0;     // grid barrier arrival counter
__device__ unsigned g_done  = 0;     // end-of-kernel reset rendezvous

union F2U { float2 f; unsigned long long u; };

__device__ __forceinline__ unsigned long long pack2(float a, float b) {
    F2U v; v.f.x = a; v.f.y = b; return v.u;
}
__device__ __forceinline__ float2 unpack2(unsigned long long u) {
    F2U v; v.u = u; return v.f;
}
// Blackwell packed fp32x2 FMA: 2 exact fp32 MACs per instruction.
__device__ __forceinline__ unsigned long long ffma2(unsigned long long a,
                                                    unsigned long long b,
                                                    unsigned long long c) {
    unsigned long long d;
    asm("fma.rn.f32x2 %0, %1, %2, %3;" : "=l"(d) : "l"(a), "l"(b), "l"(c));
    return d;
}
__device__ __forceinline__ float redsum(unsigned long long a) {
    float2 v = unpack2(a); return v.x + v.y;
}
__device__ __forceinline__ float sigf(float x) {
    return __fdividef(1.0f, 1.0f + __expf(-x));
}
__device__ __forceinline__ float tanhf_(float x) {
    return fmaf(2.0f, sigf(2.0f * x), -1.0f);
}

// Grid-wide barrier over NCTA co-resident CTAs (1 CTA/SM).
__device__ __forceinline__ void grid_bar(unsigned target) {
    __syncthreads();
    if (threadIdx.x == 0) {
        __threadfence();
        atomicAdd(&g_count, 1u);
        unsigned v;
        do {
            asm volatile("ld.acquire.gpu.u32 %0, [%1];" : "=r"(v) : "l"(&g_count));
        } while (v < target);
    }
    __syncthreads();
}

__global__ void __launch_bounds__(NTH, 1)
lstm_fused(const float* __restrict__ x,
           const float* __restrict__ Wih0, const float* __restrict__ Whh0,
           const float* __restrict__ bih0, const float* __restrict__ bhh0,
           const float* __restrict__ Wih1, const float* __restrict__ Whh1,
           const float* __restrict__ bih1, const float* __restrict__ bhh1,
           const float* __restrict__ Wlin, const float* __restrict__ blin,
           float* __restrict__ out)
{
    // Pair-packed weight slabs (8 KB each):
    // sW[k2*4+q].x = {W[q*H+u0][2k2], W[q*H+u0][2k2+1]}, .y same for u0+1
    __shared__ ulonglong2 sW0 [K2n * 4];
    __shared__ ulonglong2 sW1i[K2n * 4];
    __shared__ ulonglong2 sW1h[K2n * 4];
    // 2-slot k-split reduction buffer: index (i4*2 + slot)*128 + b2  (16 KB)
    __shared__ float4 sRed[4 * 2 * 128];
    __shared__ float sWx[8], sB0[8], sB1[8];   // per-CTA gate consts: [q*2+j]

    const int tid = threadIdx.x;
    const int b2  = tid & 127;     // batch slots {b2, b2+128}
    const int ks  = tid >> 7;      // k-split group 0..3 (warp-uniform)
    const int cta = blockIdx.x;
    const int u0  = 2 * cta;       // owned unit pair (both layers)

    // ---- one-time staging ----
    for (int i = cta * NTH + tid; i < Bsz * Tlen; i += NCTA * NTH) {
        int b = i >> 10, t = i & (Tlen - 1);
        g_xT[t * Bsz + b] = x[i];            // coalesced read, scattered write
    }
    for (int e = tid; e < K2n * 4; e += NTH) {
        int k2 = e >> 2, q = e & 3;
        int base = (q * Hdim + u0) * Hdim + 2 * k2;
        sW0[e]  = make_ulonglong2(pack2(Whh0[base],        Whh0[base + 1]),
                                  pack2(Whh0[base + Hdim], Whh0[base + Hdim + 1]));
        sW1i[e] = make_ulonglong2(pack2(Wih1[base],        Wih1[base + 1]),
                                  pack2(Wih1[base + Hdim], Wih1[base + Hdim + 1]));
        sW1h[e] = make_ulonglong2(pack2(Whh1[base],        Whh1[base + 1]),
                                  pack2(Whh1[base + Hdim], Whh1[base + Hdim + 1]));
    }
    if (tid < 8) {
        int q = tid >> 1, j = tid & 1;
        int g = q * Hdim + u0 + j;
        sWx[tid] = Wih0[g];                  // input dim == 1
        sB0[tid] = bih0[g] + bhh0[g];
        sB1[tid] = bih1[g] + bhh1[g];
    }
    const float bl = __ldg(blin);

    if (tid < Bsz) {                         // zero initial h (parity-0)
        g_h0p[0][cta * Bsz + tid] = 0ull;
        g_h1p[0][cta * Bsz + tid] = 0ull;
    }
    float c0r[2][2] = {{0.f,0.f},{0.f,0.f}}; // [unit j][batch m] (ks==0 only)
    float c1r[2][2] = {{0.f,0.f},{0.f,0.f}};

    unsigned nbar = 1;
    grid_bar(nbar * NCTA); nbar++;           // init barrier (also orders staging)

    const int k0 = ks * K2PT;

    for (int t = 0; t < Tlen; ++t) {
        const int pr = t & 1, nx = pr ^ 1;
        float s[16];                         // partial gate sums [q*4 + j*2 + m]

        // ================= layer 0: gates = h0_prev @ Whh0^T (+x, bias) ======
        {
            unsigned long long aA[4][2], aB[4][2];
            #pragma unroll
            for (int q = 0; q < 4; ++q) {
                aA[q][0]=0ull; aA[q][1]=0ull; aB[q][0]=0ull; aB[q][1]=0ull;
            }
            const unsigned long long* __restrict__ hp = g_h0p[pr];
            #pragma unroll 4
            for (int i = 0; i < K2PT; ++i) {
                int k2 = k0 + i;
                unsigned long long hA = __ldcg(hp + k2 * Bsz + b2);
                unsigned long long hB = __ldcg(hp + k2 * Bsz + b2 + 128);
                #pragma unroll
                for (int q = 0; q < 4; ++q) {
                    ulonglong2 w = sW0[k2 * 4 + q];      // broadcast LDS.128
                    aA[q][0] = ffma2(hA, w.x, aA[q][0]);
                    aA[q][1] = ffma2(hA, w.y, aA[q][1]);
                    aB[q][0] = ffma2(hB, w.x, aB[q][0]);
                    aB[q][1] = ffma2(hB, w.y, aB[q][1]);
                }
            }
            #pragma unroll
            for (int q = 0; q < 4; ++q)
                #pragma unroll
                for (int j = 0; j < 2; ++j) {
                    s[q*4 + j*2 + 0] = redsum(aA[q][j]);
                    s[q*4 + j*2 + 1] = redsum(aB[q][j]);
                }
        }
        // -- 4-way k reduction (2 rounds through 2-slot buffer) --
        if (ks == 1 || ks == 2) {
            int slot = ks - 1;
            #pragma unroll
            for (int i4 = 0; i4 < 4; ++i4)
                sRed[(i4*2 + slot)*128 + b2] =
                    make_float4(s[4*i4], s[4*i4+1], s[4*i4+2], s[4*i4+3]);
        }
        __syncthreads();
        if (ks == 0) {
            #pragma unroll
            for (int i4 = 0; i4 < 4; ++i4) {
                float4 v0 = sRed[(i4*2+0)*128 + b2];
                float4 v1 = sRed[(i4*2+1)*128 + b2];
                s[4*i4+0] += v0.x + v1.x;  s[4*i4+1] += v0.y + v1.y;
                s[4*i4+2] += v0.z + v1.z;  s[4*i4+3] += v0.w + v1.w;
            }
        }
        __syncthreads();
        if (ks == 3) {
            #pragma unroll
            for (int i4 = 0; i4 < 4; ++i4)
                sRed[(i4*2)*128 + b2] =
                    make_float4(s[4*i4], s[4*i4+1], s[4*i4+2], s[4*i4+3]);
        }
        __syncthreads();
        if (ks == 0) {
            #pragma unroll
            for (int i4 = 0; i4 < 4; ++i4) {
                float4 v = sRed[(i4*2)*128 + b2];
                s[4*i4+0] += v.x; s[4*i4+1] += v.y;
                s[4*i4+2] += v.z; s[4*i4+3] += v.w;
            }
            // -- activations + h0 store (ks==0 threads own cell state) --
            #pragma unroll
            for (int m = 0; m < 2; ++m) {
                float xv = __ldg(&g_xT[t * Bsz + b2 + m*128]);
                float hw[2];
                #pragma unroll
                for (int j = 0; j < 2; ++j) {
                    float gi = s[0*4+j*2+m] + fmaf(sWx[0*2+j], xv, sB0[0*2+j]);
                    float gf = s[1*4+j*2+m] + fmaf(sWx[1*2+j], xv, sB0[1*2+j]);
                    float gg = s[2*4+j*2+m] + fmaf(sWx[2*2+j], xv, sB0[2*2+j]);
                    float go = s[3*4+j*2+m] + fmaf(sWx[3*2+j], xv, sB0[3*2+j]);
                    float cn = sigf(gf) * c0r[j][m] + sigf(gi) * tanhf_(gg);
                    c0r[j][m] = cn;
                    hw[j] = sigf(go) * tanhf_(cn);
                }
                g_h0p[nx][cta * Bsz + b2 + m*128] = pack2(hw[0], hw[1]);
            }
        }
        grid_bar(nbar * NCTA); nbar++;       // all h0_new published

        // ============ layer 1: gates = h0_new @ Wih1^T + h1_prev @ Whh1^T ====
        {
            unsigned long long aA[4][2], aB[4][2];
            #pragma unroll
            for (int q = 0; q < 4; ++q) {
                aA[q][0]=0ull; aA[q][1]=0ull; aB[q][0]=0ull; aB[q][1]=0ull;
            }
            const unsigned long long* __restrict__ ha = g_h0p[nx];
            const unsigned long long* __restrict__ hb = g_h1p[pr];
            #pragma unroll 2
            for (int i = 0; i < K2PT; ++i) {
                int k2 = k0 + i;
                unsigned long long vaA = __ldcg(ha + k2 * Bsz + b2);
                unsigned long long vaB = __ldcg(ha + k2 * Bsz + b2 + 128);
                unsigned long long vbA = __ldcg(hb + k2 * Bsz + b2);
                unsigned long long vbB = __ldcg(hb + k2 * Bsz + b2 + 128);
                #pragma unroll
                for (int q = 0; q < 4; ++q) {
                    ulonglong2 wi = sW1i[k2 * 4 + q];
                    ulonglong2 wh = sW1h[k2 * 4 + q];
                    aA[q][0] = ffma2(vaA, wi.x, aA[q][0]);
                    aA[q][1] = ffma2(vaA, wi.y, aA[q][1]);
                    aB[q][0] = ffma2(vaB, wi.x, aB[q][0]);
                    aB[q][1] = ffma2(vaB, wi.y, aB[q][1]);
                    aA[q][0] = ffma2(vbA, wh.x, aA[q][0]);
                    aA[q][1] = ffma2(vbA, wh.y, aA[q][1]);
                    aB[q][0] = ffma2(vbB, wh.x, aB[q][0]);
                    aB[q][1] = ffma2(vbB, wh.y, aB[q][1]);
                }
            }
            #pragma unroll
            for (int q = 0; q < 4; ++q)
                #pragma unroll
                for (int j = 0; j < 2; ++j) {
                    s[q*4 + j*2 + 0] = redsum(aA[q][j]);
                    s[q*4 + j*2 + 1] = redsum(aB[q][j]);
                }
        }
        if (ks == 1 || ks == 2) {
            int slot = ks - 1;
            #pragma unroll
            for (int i4 = 0; i4 < 4; ++i4)
                sRed[(i4*2 + slot)*128 + b2] =
                    make_float4(s[4*i4], s[4*i4+1], s[4*i4+2], s[4*i4+3]);
        }
        __syncthreads();
        if (ks == 0) {
            #pragma unroll
            for (int i4 = 0; i4 < 4; ++i4) {
                float4 v0 = sRed[(i4*2+0)*128 + b2];
                float4 v1 = sRed[(i4*2+1)*128 + b2];
                s[4*i4+0] += v0.x + v1.x;  s[4*i4+1] += v0.y + v1.y;
                s[4*i4+2] += v0.z + v1.z;  s[4*i4+3] += v0.w + v1.w;
            }
        }
        __syncthreads();
        if (ks == 3) {
            #pragma unroll
            for (int i4 = 0; i4 < 4; ++i4)
                sRed[(i4*2)*128 + b2] =
                    make_float4(s[4*i4], s[4*i4+1], s[4*i4+2], s[4*i4+3]);
        }
        __syncthreads();
        if (ks == 0) {
            #pragma unroll
            for (int i4 = 0; i4 < 4; ++i4) {
                float4 v = sRed[(i4*2)*128 + b2];
                s[4*i4+0] += v.x; s[4*i4+1] += v.y;
                s[4*i4+2] += v.z; s[4*i4+3] += v.w;
            }
            #pragma unroll
            for (int m = 0; m < 2; ++m) {
                float hw[2];
                #pragma unroll
                for (int j = 0; j < 2; ++j) {
                    float gi = s[0*4+j*2+m] + sB1[0*2+j];
                    float gf = s[1*4+j*2+m] + sB1[1*2+j];
                    float gg = s[2*4+j*2+m] + sB1[2*2+j];
                    float go = s[3*4+j*2+m] + sB1[3*2+j];
                    float cn = sigf(gf) * c1r[j][m] + sigf(gi) * tanhf_(gg);
                    c1r[j][m] = cn;
                    hw[j] = sigf(go) * tanhf_(cn);
                }
                g_h1p[nx][cta * Bsz + b2 + m*128] = pack2(hw[0], hw[1]);
            }
        }
        grid_bar(nbar * NCTA); nbar++;       // all h1_new published

        // ============ output: out[bb, t] = h1[t, bb, :] . Wlin + blin ========
        {
            if (tid < 256) {
                const unsigned long long* __restrict__ hc = g_h1p[nx];
                int half = tid >> 7;         // 0..127 -> batch u0, 128..255 -> u0+1
                int kk   = tid & 127;
                int bb   = u0 + half;
                float2 hv = unpack2(__ldcg(hc + kk * Bsz + bb));
                float part = hv.x * __ldg(Wlin + 2*kk) + hv.y * __ldg(Wlin + 2*kk + 1);
                #pragma unroll
                for (int off = 16; off > 0; off >>= 1)
                    part += __shfl_down_sync(0xffffffffu, part, off);
                if ((tid & 31) == 0)
                    reinterpret_cast<float*>(sRed)[tid >> 5] = part;
            }
            __syncthreads();
            if (tid == 0) {
                const float* sO = reinterpret_cast<const float*>(sRed);
                out[(u0 + 0) * Tlen + t] = sO[0] + sO[1] + sO[2] + sO[3] + bl;
                out[(u0 + 1) * Tlen + t] = sO[4] + sO[5] + sO[6] + sO[7] + bl;
            }
            __syncthreads();                 // protect sRed reuse next step
        }
    }

    // Reset barrier counters for the next launch.
    __syncthreads();
    if (tid == 0) {
        __threadfence();
        unsigned old = atomicAdd(&g_done, 1u);
        if (old == NCTA - 1) {
            atomicExch(&g_count, 0u);
            atomicExch(&g_done, 0u);
        }
    }
}

extern "C" void kernel_launch(void* const* d_in, const int* in_sizes, int n_in,
                              void* d_out, int out_size) {
    (void)in_sizes; (void)n_in; (void)out_size;
    lstm_fused<<<NCTA, NTH>>>(
        (const float*)d_in[0],
        (const float*)d_in[1], (const float*)d_in[2],
        (const float*)d_in[3], (const float*)d_in[4],
        (const float*)d_in[5], (const float*)d_in[6],
        (const float*)d_in[7], (const float*)d_in[8],
        (const float*)d_in[9], (const float*)d_in[10],
        (float*)d_out);
}

// round 6
// speedup vs baseline: 1.5211x; 1.1195x over previous
#include <cuda_runtime.h>
#include <math.h>

#define NCTA 128
#define NTH  512
#define Bsz  256
#define Tlen 1024
#define Hdim 256
#define K2n  128   // Hdim/2 unit-pairs (k dimension in f32x2 lanes)
#define K2PT 32    // K2n / 4 k-split groups

// Persistent state, exchanged through L2 (double-buffered by step parity).
// u64 layout: [pair k2][batch b] packs {h[2k2][b], h[2k2+1][b]}.
__device__ unsigned long long g_h0p[2][K2n * Bsz];
__device__ unsigned long long g_h1p[2][K2n * Bsz];
__device__ float g_xT[Tlen * Bsz];   // x transposed: [t][b]
__device__ unsigned g_cntA = 0;      // barrier line A (h0 publishes)
__device__ unsigned g_cntB = 0;      // barrier line B (h1 publishes)
__device__ unsigned g_done = 0;      // end-of-kernel reset rendezvous

union F2U { float2 f; unsigned long long u; };

__device__ __forceinline__ unsigned long long pack2(float a, float b) {
    F2U v; v.f.x = a; v.f.y = b; return v.u;
}
__device__ __forceinline__ float2 unpack2(unsigned long long u) {
    F2U v; v.u = u; return v.f;
}
// Blackwell packed fp32x2 FMA: 2 exact fp32 MACs per instruction.
__device__ __forceinline__ unsigned long long ffma2(unsigned long long a,
                                                    unsigned long long b,
                                                    unsigned long long c) {
    unsigned long long d;
    asm("fma.rn.f32x2 %0, %1, %2, %3;" : "=l"(d) : "l"(a), "l"(b), "l"(c));
    return d;
}
__device__ __forceinline__ float redsum(unsigned long long a) {
    float2 v = unpack2(a); return v.x + v.y;
}
__device__ __forceinline__ float sigf(float x) {
    return __fdividef(1.0f, 1.0f + __expf(-x));
}
__device__ __forceinline__ float tanhf_(float x) {
    return fmaf(2.0f, sigf(2.0f * x), -1.0f);
}

// Split-phase grid barrier (NCTA co-resident CTAs, 1/SM).
__device__ __forceinline__ void bar_arrive(unsigned* c) {
    __syncthreads();                       // CTA's stores done
    if (threadIdx.x == 0) { __threadfence(); atomicAdd(c, 1u); }
}
__device__ __forceinline__ void bar_wait(unsigned* c, unsigned target) {
    if (threadIdx.x == 0) {
        unsigned v;
        do {
            asm volatile("ld.acquire.gpu.u32 %0, [%1];" : "=r"(v) : "l"(c));
        } while (v < target);
    }
    __syncthreads();
}

// ---- layer-0 matvec slice + one-round k reduction ----
// Returns gate partial-sums float4 {i,f,g,o} for this thread's (j,m) combo.
__device__ __forceinline__ float4 mat_l0(const unsigned long long* __restrict__ hp,
                                         const ulonglong2* __restrict__ sW,
                                         float4* __restrict__ sRed,
                                         int b2, int ks, int k0) {
    unsigned long long aA[4][2], aB[4][2];
    #pragma unroll
    for (int q = 0; q < 4; ++q) { aA[q][0]=0ull; aA[q][1]=0ull; aB[q][0]=0ull; aB[q][1]=0ull; }
    #pragma unroll 8
    for (int i = 0; i < K2PT; ++i) {
        int k2 = k0 + i;
        unsigned long long hA = __ldcg(hp + k2 * Bsz + b2);
        unsigned long long hB = __ldcg(hp + k2 * Bsz + b2 + 128);
        #pragma unroll
        for (int q = 0; q < 4; ++q) {
            ulonglong2 w = sW[k2 * 4 + q];           // broadcast LDS.128
            aA[q][0] = ffma2(hA, w.x, aA[q][0]);
            aA[q][1] = ffma2(hA, w.y, aA[q][1]);
            aB[q][0] = ffma2(hB, w.x, aB[q][0]);
            aB[q][1] = ffma2(hB, w.y, aB[q][1]);
        }
    }
    #pragma unroll
    for (int jj = 0; jj < 2; ++jj) {
        sRed[(ks*4 + jj*2 + 0)*128 + b2] =
            make_float4(redsum(aA[0][jj]), redsum(aA[1][jj]),
                        redsum(aA[2][jj]), redsum(aA[3][jj]));
        sRed[(ks*4 + jj*2 + 1)*128 + b2] =
            make_float4(redsum(aB[0][jj]), redsum(aB[1][jj]),
                        redsum(aB[2][jj]), redsum(aB[3][jj]));
    }
    __syncthreads();
    float4 s = sRed[(0*4 + ks)*128 + b2];
    #pragma unroll
    for (int g = 1; g < 4; ++g) {
        float4 v = sRed[(g*4 + ks)*128 + b2];
        s.x += v.x; s.y += v.y; s.z += v.z; s.w += v.w;
    }
    return s;
}

// ---- layer-1 matvec slice (two input matrices) + one-round reduction ----
__device__ __forceinline__ float4 mat_l1(const unsigned long long* __restrict__ ha,
                                         const unsigned long long* __restrict__ hb,
                                         const ulonglong2* __restrict__ sWi,
                                         const ulonglong2* __restrict__ sWh,
                                         float4* __restrict__ sRed,
                                         int b2, int ks, int k0) {
    unsigned long long aA[4][2], aB[4][2];
    #pragma unroll
    for (int q = 0; q < 4; ++q) { aA[q][0]=0ull; aA[q][1]=0ull; aB[q][0]=0ull; aB[q][1]=0ull; }
    #pragma unroll 4
    for (int i = 0; i < K2PT; ++i) {
        int k2 = k0 + i;
        unsigned long long vaA = __ldcg(ha + k2 * Bsz + b2);
        unsigned long long vaB = __ldcg(ha + k2 * Bsz + b2 + 128);
        unsigned long long vbA = __ldcg(hb + k2 * Bsz + b2);
        unsigned long long vbB = __ldcg(hb + k2 * Bsz + b2 + 128);
        #pragma unroll
        for (int q = 0; q < 4; ++q) {
            ulonglong2 wi = sWi[k2 * 4 + q];
            ulonglong2 wh = sWh[k2 * 4 + q];
            aA[q][0] = ffma2(vaA, wi.x, aA[q][0]);
            aA[q][1] = ffma2(vaA, wi.y, aA[q][1]);
            aB[q][0] = ffma2(vaB, wi.x, aB[q][0]);
            aB[q][1] = ffma2(vaB, wi.y, aB[q][1]);
            aA[q][0] = ffma2(vbA, wh.x, aA[q][0]);
            aA[q][1] = ffma2(vbA, wh.y, aA[q][1]);
            aB[q][0] = ffma2(vbB, wh.x, aB[q][0]);
            aB[q][1] = ffma2(vbB, wh.y, aB[q][1]);
        }
    }
    #pragma unroll
    for (int jj = 0; jj < 2; ++jj) {
        sRed[(ks*4 + jj*2 + 0)*128 + b2] =
            make_float4(redsum(aA[0][jj]), redsum(aA[1][jj]),
                        redsum(aA[2][jj]), redsum(aA[3][jj]));
        sRed[(ks*4 + jj*2 + 1)*128 + b2] =
            make_float4(redsum(aB[0][jj]), redsum(aB[1][jj]),
                        redsum(aB[2][jj]), redsum(aB[3][jj]));
    }
    __syncthreads();
    float4 s = sRed[(0*4 + ks)*128 + b2];
    #pragma unroll
    for (int g = 1; g < 4; ++g) {
        float4 v = sRed[(g*4 + ks)*128 + b2];
        s.x += v.x; s.y += v.y; s.z += v.z; s.w += v.w;
    }
    return s;
}

__global__ void __launch_bounds__(NTH, 1)
lstm_fused(const float* __restrict__ x,
           const float* __restrict__ Wih0, const float* __restrict__ Whh0,
           const float* __restrict__ bih0, const float* __restrict__ bhh0,
           const float* __restrict__ Wih1, const float* __restrict__ Whh1,
           const float* __restrict__ bih1, const float* __restrict__ bhh1,
           const float* __restrict__ Wlin, const float* __restrict__ blin,
           float* __restrict__ out)
{
    __shared__ ulonglong2 sW0 [K2n * 4];   // 8 KB each, pair-packed
    __shared__ ulonglong2 sW1i[K2n * 4];
    __shared__ ulonglong2 sW1h[K2n * 4];
    __shared__ float4 sRed[16 * 128];      // 32 KB one-round reduction buffer
    __shared__ float sWx[8], sB0[8], sB1[8];
    __shared__ float sWlin[Hdim];
    __shared__ float sOut[8];

    const int tid = threadIdx.x;
    const int b2  = tid & 127;
    const int ks  = tid >> 7;              // 0..3 (warp-uniform)
    const int cta = blockIdx.x;
    const int u0  = 2 * cta;
    const int jmu = ks >> 1;               // unit-in-pair this thread activates
    const int mmu = ks & 1;                // batch-half this thread activates
    const int bown = b2 + mmu * 128;       // owned batch index
    const int k0  = ks * K2PT;

    // ---- one-time staging ----
    for (int i = cta * NTH + tid; i < Bsz * Tlen; i += NCTA * NTH) {
        int b = i >> 10, t = i & (Tlen - 1);
        g_xT[t * Bsz + b] = x[i];
    }
    for (int e = tid; e < K2n * 4; e += NTH) {
        int k2 = e >> 2, q = e & 3;
        int base = (q * Hdim + u0) * Hdim + 2 * k2;
        sW0[e]  = make_ulonglong2(pack2(Whh0[base],        Whh0[base + 1]),
                                  pack2(Whh0[base + Hdim], Whh0[base + Hdim + 1]));
        sW1i[e] = make_ulonglong2(pack2(Wih1[base],        Wih1[base + 1]),
                                  pack2(Wih1[base + Hdim], Wih1[base + Hdim + 1]));
        sW1h[e] = make_ulonglong2(pack2(Whh1[base],        Whh1[base + 1]),
                                  pack2(Whh1[base + Hdim], Whh1[base + Hdim + 1]));
    }
    if (tid < 8) {
        int q = tid >> 1, j = tid & 1;
        int g = q * Hdim + u0 + j;
        sWx[tid] = Wih0[g];
        sB0[tid] = bih0[g] + bhh0[g];
        sB1[tid] = bih1[g] + bhh1[g];
    }
    if (tid < Hdim) sWlin[tid] = Wlin[tid];
    const float bl = __ldg(blin);

    if (tid < Bsz) {                        // zero initial state (parity-0)
        g_h0p[0][cta * Bsz + tid] = 0ull;
        g_h1p[0][cta * Bsz + tid] = 0ull;
    }
    float c0 = 0.f, c1 = 0.f;               // distributed cell state (one per thread)

    // init barrier (line A)
    bar_arrive(&g_cntA);
    bar_wait(&g_cntA, 1u * NCTA);

    // ---- prologue: L0(0): h0p[0] -> h0p[1] ----
    {
        float4 s = mat_l0(g_h0p[0], sW0, sRed, b2, ks, k0);
        float xv = g_xT[0 * Bsz + bown];
        float gi = s.x + fmaf(sWx[0*2 + jmu], xv, sB0[0*2 + jmu]);
        float gf = s.y + fmaf(sWx[1*2 + jmu], xv, sB0[1*2 + jmu]);
        float gg = s.z + fmaf(sWx[2*2 + jmu], xv, sB0[2*2 + jmu]);
        float go = s.w + fmaf(sWx[3*2 + jmu], xv, sB0[3*2 + jmu]);
        float cn = sigf(gf) * c0 + sigf(gi) * tanhf_(gg);
        c0 = cn;
        float hw = sigf(go) * tanhf_(cn);
        ((float*)g_h0p[1])[(cta * Bsz + bown) * 2 + jmu] = hw;
        bar_arrive(&g_cntA);
        bar_wait(&g_cntA, 2u * NCTA);
    }

    for (int t = 0; t < Tlen; ++t) {
        const int pr = t & 1, nx = pr ^ 1;

        // ---- L1(t): h0p[nx] (new) + h1p[pr] -> h1p[nx] ----
        {
            float4 s = mat_l1(g_h0p[nx], g_h1p[pr], sW1i, sW1h, sRed, b2, ks, k0);
            float gi = s.x + sB1[0*2 + jmu];
            float gf = s.y + sB1[1*2 + jmu];
            float gg = s.z + sB1[2*2 + jmu];
            float go = s.w + sB1[3*2 + jmu];
            float cn = sigf(gf) * c1 + sigf(gi) * tanhf_(gg);
            c1 = cn;
            float hw = sigf(go) * tanhf_(cn);
            ((float*)g_h1p[nx])[(cta * Bsz + bown) * 2 + jmu] = hw;
        }
        bar_arrive(&g_cntB);                 // idB = t+1

        // ---- L0(t+1): h0p[nx] -> h0p[pr]  (hides B-barrier latency) ----
        if (t < Tlen - 1) {
            float4 s = mat_l0(g_h0p[nx], sW0, sRed, b2, ks, k0);
            float xv = g_xT[(t + 1) * Bsz + bown];
            float gi = s.x + fmaf(sWx[0*2 + jmu], xv, sB0[0*2 + jmu]);
            float gf = s.y + fmaf(sWx[1*2 + jmu], xv, sB0[1*2 + jmu]);
            float gg = s.z + fmaf(sWx[2*2 + jmu], xv, sB0[2*2 + jmu]);
            float go = s.w + fmaf(sWx[3*2 + jmu], xv, sB0[3*2 + jmu]);
            float cn = sigf(gf) * c0 + sigf(gi) * tanhf_(gg);
            c0 = cn;
            float hw = sigf(go) * tanhf_(cn);
            ((float*)g_h0p[pr])[(cta * Bsz + bown) * 2 + jmu] = hw;
            bar_arrive(&g_cntA);             // idA = t+3
        }

        // ---- wait for all h1(t), then output dot ----
        bar_wait(&g_cntB, (unsigned)(t + 1) * NCTA);
        {
            if (tid < 256) {
                const unsigned long long* __restrict__ hc = g_h1p[nx];
                int half = tid >> 7;         // 0..127 -> batch u0, 128..255 -> u0+1
                int kk   = tid & 127;
                int bb   = u0 + half;
                float2 hv = unpack2(__ldcg(hc + kk * Bsz + bb));
                float part = hv.x * sWlin[2*kk] + hv.y * sWlin[2*kk + 1];
                #pragma unroll
                for (int off = 16; off > 0; off >>= 1)
                    part += __shfl_down_sync(0xffffffffu, part, off);
                if ((tid & 31) == 0) sOut[tid >> 5] = part;
            }
            __syncthreads();
            if (tid == 0) {
                out[(u0 + 0) * Tlen + t] = sOut[0] + sOut[1] + sOut[2] + sOut[3] + bl;
                out[(u0 + 1) * Tlen + t] = sOut[4] + sOut[5] + sOut[6] + sOut[7] + bl;
            }
        }

        if (t < Tlen - 1)
            bar_wait(&g_cntA, (unsigned)(t + 3) * NCTA);   // h0(t+1) visible
    }

    // reset counters for next launch
    __syncthreads();
    if (tid == 0) {
        __threadfence();
        unsigned old = atomicAdd(&g_done, 1u);
        if (old == NCTA - 1) {
            atomicExch(&g_cntA, 0u);
            atomicExch(&g_cntB, 0u);
            atomicExch(&g_done, 0u);
        }
    }
}

extern "C" void kernel_launch(void* const* d_in, const int* in_sizes, int n_in,
                              void* d_out, int out_size) {
    (void)in_sizes; (void)n_in; (void)out_size;
    lstm_fused<<<NCTA, NTH>>>(
        (const float*)d_in[0],
        (const float*)d_in[1], (const float*)d_in[2],
        (const float*)d_in[3], (const float*)d_in[4],
        (const float*)d_in[5], (const float*)d_in[6],
        (const float*)d_in[7], (const float*)d_in[8],
        (const float*)d_in[9], (const float*)d_in[10],
        (float*)d_out);
}